// round 2
// baseline (speedup 1.0000x reference)
#include <cuda_runtime.h>
#include <mma.h>
#include <cstdint>
#include <cstddef>

using namespace nvcuda;

// Problem constants (fixed by the reference): B=4, S=2048, D=DK=DV=1024.
static const int ATT_B = 4;
static const int ATT_S = 2048;
static const int ATT_D = 1024;

// ---------------------------------------------------------------------------
// Scratch: __device__ globals (no cudaMalloc allowed anywhere).
// Q,K,V: [B*S, D] fp32 each (32 MB). S_attn: [B, S, S] fp32 (64 MB).
// ---------------------------------------------------------------------------
__device__ float g_Q[(size_t)4 * 2048 * 1024];
__device__ float g_K[(size_t)4 * 2048 * 1024];
__device__ float g_V[(size_t)4 * 2048 * 1024];
__device__ float g_S[(size_t)4 * 2048 * 2048];

// ---------------------------------------------------------------------------
// tf32 wmma GEMM: C[M,N] = scale * (A[M,K] @ op(B)) + bias
//   BTRANS=false: B is [K,N] row-major
//   BTRANS=true : B is [N,K] row-major, used as B^T (i.e. C = A @ B^T)
// Block tile 128x128, K-chunk 32, 8 warps (2x4), warp tile 64x32,
// wmma m16n16k8 tf32 fragments. All dims assumed multiples of tile sizes.
// ---------------------------------------------------------------------------
constexpr int BM = 128, BN = 128, BK = 32;
constexpr int LDAS   = 36;   // A smem ld (floats), pad vs 32 banks
constexpr int LDBS_T = 36;   // B smem ld for col-major (BTRANS) use
constexpr int LDBS_N = 132;  // B smem ld for row-major use
constexpr int STG_LD = 20;   // epilogue staging ld (multiple of 4)

template <bool BTRANS>
__global__ void __launch_bounds__(256) gemm_tf32(
    const float* __restrict__ A, const float* __restrict__ Bm,
    const float* __restrict__ bias, float* __restrict__ C,
    int M, int N, int K,
    size_t strA, size_t strB, size_t strC, float scale)
{
    __shared__ float As[BM * LDAS];          // 128x32 tile, ld 36
    __shared__ float Bs[BM * LDAS];          // 128x36 >= 32x132 floats, reused both ways
    __shared__ float stage[8 * 16 * STG_LD]; // per-warp 16x16 epilogue staging

    A  += (size_t)blockIdx.z * strA;
    Bm += (size_t)blockIdx.z * strB;
    C  += (size_t)blockIdx.z * strC;

    const int m0   = blockIdx.y * BM;
    const int n0   = blockIdx.x * BN;
    const int tid  = threadIdx.x;
    const int wid  = tid >> 5;
    const int lane = tid & 31;
    const int mw   = (wid >> 2) * 64;  // warp row offset within block tile
    const int nw   = (wid & 3) * 32;   // warp col offset within block tile

    wmma::fragment<wmma::accumulator, 16, 16, 8, float> acc[4][2];
#pragma unroll
    for (int i = 0; i < 4; i++)
#pragma unroll
        for (int j = 0; j < 2; j++)
            wmma::fill_fragment(acc[i][j], 0.0f);

    const int ar = tid >> 3;         // A/B-trans tile row base (advances by 32 per chunk)
    const int ac = (tid & 7) * 4;    // A/B-trans tile col (float4)
    const int br = tid >> 5;         // B row-major tile row base (advances by 8)
    const int bc = (tid & 31) * 4;   // B row-major tile col (float4)

    for (int k0 = 0; k0 < K; k0 += BK) {
        float4 av[4], bv[4];
#pragma unroll
        for (int i = 0; i < 4; i++)
            av[i] = *reinterpret_cast<const float4*>(
                &A[(size_t)(m0 + ar + i * 32) * K + k0 + ac]);
        if constexpr (BTRANS) {
#pragma unroll
            for (int i = 0; i < 4; i++)
                bv[i] = *reinterpret_cast<const float4*>(
                    &Bm[(size_t)(n0 + ar + i * 32) * K + k0 + ac]);
        } else {
#pragma unroll
            for (int i = 0; i < 4; i++)
                bv[i] = *reinterpret_cast<const float4*>(
                    &Bm[(size_t)(k0 + br + i * 8) * N + n0 + bc]);
        }

        __syncthreads();  // previous iteration's mma reads done

#pragma unroll
        for (int i = 0; i < 4; i++) {
            float* p = &As[(ar + i * 32) * LDAS + ac];
            p[0] = wmma::__float_to_tf32(av[i].x);
            p[1] = wmma::__float_to_tf32(av[i].y);
            p[2] = wmma::__float_to_tf32(av[i].z);
            p[3] = wmma::__float_to_tf32(av[i].w);
        }
        if constexpr (BTRANS) {
#pragma unroll
            for (int i = 0; i < 4; i++) {
                float* p = &Bs[(ar + i * 32) * LDBS_T + ac];
                p[0] = wmma::__float_to_tf32(bv[i].x);
                p[1] = wmma::__float_to_tf32(bv[i].y);
                p[2] = wmma::__float_to_tf32(bv[i].z);
                p[3] = wmma::__float_to_tf32(bv[i].w);
            }
        } else {
#pragma unroll
            for (int i = 0; i < 4; i++) {
                float* p = &Bs[(br + i * 8) * LDBS_N + bc];
                p[0] = wmma::__float_to_tf32(bv[i].x);
                p[1] = wmma::__float_to_tf32(bv[i].y);
                p[2] = wmma::__float_to_tf32(bv[i].z);
                p[3] = wmma::__float_to_tf32(bv[i].w);
            }
        }
        __syncthreads();

#pragma unroll
        for (int ks = 0; ks < 4; ks++) {
            const int ko = ks * 8;
            wmma::fragment<wmma::matrix_a, 16, 16, 8, wmma::precision::tf32,
                           wmma::row_major> af[4];
#pragma unroll
            for (int i = 0; i < 4; i++)
                wmma::load_matrix_sync(af[i], &As[(mw + i * 16) * LDAS + ko], LDAS);

            if constexpr (BTRANS) {
                wmma::fragment<wmma::matrix_b, 16, 16, 8, wmma::precision::tf32,
                               wmma::col_major> bf[2];
#pragma unroll
                for (int j = 0; j < 2; j++)
                    wmma::load_matrix_sync(bf[j], &Bs[(nw + j * 16) * LDBS_T + ko], LDBS_T);
#pragma unroll
                for (int i = 0; i < 4; i++)
#pragma unroll
                    for (int j = 0; j < 2; j++)
                        wmma::mma_sync(acc[i][j], af[i], bf[j], acc[i][j]);
            } else {
                wmma::fragment<wmma::matrix_b, 16, 16, 8, wmma::precision::tf32,
                               wmma::row_major> bf[2];
#pragma unroll
                for (int j = 0; j < 2; j++)
                    wmma::load_matrix_sync(bf[j], &Bs[ko * LDBS_N + nw + j * 16], LDBS_N);
#pragma unroll
                for (int i = 0; i < 4; i++)
#pragma unroll
                    for (int j = 0; j < 2; j++)
                        wmma::mma_sync(acc[i][j], af[i], bf[j], acc[i][j]);
            }
        }
    }

    // Epilogue: per-warp stage through smem so bias can be applied per-column.
    float* stg = &stage[wid * 16 * STG_LD];
#pragma unroll
    for (int i = 0; i < 4; i++) {
#pragma unroll
        for (int j = 0; j < 2; j++) {
            wmma::store_matrix_sync(stg, acc[i][j], STG_LD, wmma::mem_row_major);
            __syncwarp();
#pragma unroll
            for (int l = 0; l < 8; l++) {
                const int e = lane + l * 32;
                const int r = e >> 4, c = e & 15;
                const int col = n0 + nw + j * 16 + c;
                float v = stg[r * STG_LD + c] * scale;
                if (bias) v += bias[col];
                C[(size_t)(m0 + mw + i * 16 + r) * N + col] = v;
            }
            __syncwarp();
        }
    }
}

// ---------------------------------------------------------------------------
// Row softmax over 2048 columns. One block (256 threads) per row; each thread
// owns 8 elements kept in registers (one global read, one write).
// ---------------------------------------------------------------------------
__global__ void __launch_bounds__(256) softmax2048(float* __restrict__ A)
{
    float* row = A + (size_t)blockIdx.x * 2048;
    const int tid = threadIdx.x;
    const int lane = tid & 31, wid = tid >> 5;
    __shared__ float redm[8];
    __shared__ float reds[8];

    float v[8];
    float mx = -3.4e38f;
#pragma unroll
    for (int i = 0; i < 8; i++) {
        v[i] = row[tid + i * 256];
        mx = fmaxf(mx, v[i]);
    }
#pragma unroll
    for (int o = 16; o; o >>= 1) mx = fmaxf(mx, __shfl_xor_sync(0xffffffffu, mx, o));
    if (lane == 0) redm[wid] = mx;
    __syncthreads();
    float m = redm[0];
#pragma unroll
    for (int i = 1; i < 8; i++) m = fmaxf(m, redm[i]);

    float s = 0.0f;
#pragma unroll
    for (int i = 0; i < 8; i++) {
        v[i] = __expf(v[i] - m);
        s += v[i];
    }
#pragma unroll
    for (int o = 16; o; o >>= 1) s += __shfl_xor_sync(0xffffffffu, s, o);
    if (lane == 0) reds[wid] = s;
    __syncthreads();
    float t = 0.0f;
#pragma unroll
    for (int i = 0; i < 8; i++) t += reds[i];
    const float inv = 1.0f / t;
#pragma unroll
    for (int i = 0; i < 8; i++) row[tid + i * 256] = v[i] * inv;
}

// ---------------------------------------------------------------------------
// kernel_launch: X, W_q, W_k, W_v, b_q, b_k, b_v  ->  O [B,S,DV] fp32
// ---------------------------------------------------------------------------
extern "C" void kernel_launch(void* const* d_in, const int* in_sizes, int n_in,
                              void* d_out, int out_size)
{
    (void)in_sizes; (void)n_in; (void)out_size;
    const float* X  = (const float*)d_in[0];
    const float* Wq = (const float*)d_in[1];
    const float* Wk = (const float*)d_in[2];
    const float* Wv = (const float*)d_in[3];
    const float* bq = (const float*)d_in[4];
    const float* bk = (const float*)d_in[5];
    const float* bv = (const float*)d_in[6];
    float* O = (float*)d_out;

    float *Q, *Kb, *V, *S;
    cudaGetSymbolAddress((void**)&Q,  g_Q);
    cudaGetSymbolAddress((void**)&Kb, g_K);
    cudaGetSymbolAddress((void**)&V,  g_V);
    cudaGetSymbolAddress((void**)&S,  g_S);

    const int BS = ATT_B * ATT_S;              // 8192
    const size_t sQK = (size_t)ATT_S * ATT_D;  // 2048*1024 per-batch stride
    const size_t sSS = (size_t)ATT_S * ATT_S;  // 2048*2048 per-batch stride
    const float qk_scale = 0.03125f;           // 1/sqrt(1024)

    // Projections: [8192,1024] = X[8192,1024] @ W[1024,1024] + b
    dim3 gproj(ATT_D / BN, BS / BM, 1);        // (8, 64, 1)
    gemm_tf32<false><<<gproj, 256>>>(X, Wq, bq, Q,  BS, ATT_D, ATT_D, 0, 0, 0, 1.0f);
    gemm_tf32<false><<<gproj, 256>>>(X, Wk, bk, Kb, BS, ATT_D, ATT_D, 0, 0, 0, 1.0f);
    gemm_tf32<false><<<gproj, 256>>>(X, Wv, bv, V,  BS, ATT_D, ATT_D, 0, 0, 0, 1.0f);

    // Logits: per batch S[b] = (Q[b] @ K[b]^T) * 1/sqrt(DK)
    dim3 glog(ATT_S / BN, ATT_S / BM, ATT_B);  // (16, 16, 4)
    gemm_tf32<true><<<glog, 256>>>(Q, Kb, nullptr, S, ATT_S, ATT_S, ATT_D,
                                   sQK, sQK, sSS, qk_scale);

    // Softmax over keys (axis=2), one block per row
    softmax2048<<<ATT_B * ATT_S, 256>>>(S);

    // Output: per batch O[b] = S[b] @ V[b]
    dim3 gout(ATT_D / BN, ATT_S / BM, ATT_B);  // (8, 16, 4)
    gemm_tf32<false><<<gout, 256>>>(S, V, nullptr, O, ATT_S, ATT_D, ATT_S,
                                    sSS, sQK, sQK, 1.0f);
}

// round 6
// speedup vs baseline: 3.4353x; 3.4353x over previous
#include <cuda_runtime.h>
#include <cuda_fp16.h>
#include <mma.h>
#include <cstdint>
#include <cstddef>

using namespace nvcuda;

// B=4, S=2048, D=DK=DV=1024. Scratch: __device__ globals only.
__device__ __half g_Xh[(size_t)8192 * 1024];          // fp16 X
__device__ __half g_Wh[(size_t)3 * 1024 * 1024];      // fp16 Wq|Wk|Wv
__device__ __half g_Qh[(size_t)8192 * 1024];
__device__ __half g_Kh[(size_t)8192 * 1024];
__device__ __half g_Vh[(size_t)8192 * 1024];
__device__ float  g_S [(size_t)4 * 2048 * 2048];      // logits fp32
__device__ __half g_P [(size_t)4 * 2048 * 2048];      // probs fp16

__device__ __forceinline__ void cp16(uint32_t dst, const void* src) {
    asm volatile("cp.async.cg.shared.global [%0], [%1], 16;"
                 :: "r"(dst), "l"(src) : "memory");
}
__device__ __forceinline__ uint32_t smem_u32(const void* p) {
    uint32_t a;
    asm("{ .reg .u64 t; cvta.to.shared.u64 t, %1; cvt.u32.u64 %0, t; }"
        : "=r"(a) : "l"(p));
    return a;
}

// ---------------------------------------------------------------------------
// fp16 wmma GEMM, 128x128 CTA tile, BK=64, 3-stage cp.async pipeline.
//   BTRANS=true : B is [N,K] row-major -> C = A @ B^T
//   BTRANS=false: B is [K,N] row-major -> C = A @ B
//   OUTH: write __half C (with bias), else float C (scale applied).
// smem per stage: A 128x(64 pad 80) fp16 = 20480 B, B <= 20480 B.
// ---------------------------------------------------------------------------
constexpr int LDA   = 80;    // halves (A and B-trans tiles)
constexpr int LDBN  = 144;   // halves (B non-trans tile rows of 128)
constexpr int STAGE = 40960; // bytes per stage
constexpr int SMEM_TOTAL = 3 * STAGE;  // 122880

template <bool BTRANS, bool OUTH>
__global__ void __launch_bounds__(256) gemm_h(
    const __half* __restrict__ A, const __half* __restrict__ Bm,
    const float* __restrict__ bias, void* __restrict__ Cv,
    int N_, int K, size_t strA, size_t strB, size_t strC, float scale)
{
    extern __shared__ char smem[];
    const uint32_t sbase = smem_u32(smem);
    const int tid = threadIdx.x, wid = tid >> 5, lane = tid & 31;

    A  += (size_t)blockIdx.z * strA;
    Bm += (size_t)blockIdx.z * strB;
    const int m0 = blockIdx.y * 128;
    const int n0 = blockIdx.x * 128;
    const int mw = (wid >> 2) * 64;
    const int nw = (wid & 3) * 32;
    const int nch = K >> 6;

    wmma::fragment<wmma::accumulator, 16, 16, 16, float> acc[4][2];
#pragma unroll
    for (int i = 0; i < 4; i++)
#pragma unroll
        for (int j = 0; j < 2; j++) wmma::fill_fragment(acc[i][j], 0.0f);

    auto load_chunk = [&](int c, int s) {
        const uint32_t sA = sbase + (uint32_t)s * STAGE;
        const uint32_t sB = sA + 20480u;
#pragma unroll
        for (int i = 0; i < 4; i++) {                 // A: 128 rows x 64 halves
            int lin = tid + i * 256;
            int r = lin >> 3, c8 = (lin & 7) * 8;
            cp16(sA + (uint32_t)(r * 160 + c8 * 2),
                 A + (size_t)(m0 + r) * K + c * 64 + c8);
        }
        if (BTRANS) {                                 // B: 128 rows x 64 halves
#pragma unroll
            for (int i = 0; i < 4; i++) {
                int lin = tid + i * 256;
                int r = lin >> 3, c8 = (lin & 7) * 8;
                cp16(sB + (uint32_t)(r * 160 + c8 * 2),
                     Bm + (size_t)(n0 + r) * K + c * 64 + c8);
            }
        } else {                                      // B: 64 rows x 128 halves
#pragma unroll
            for (int i = 0; i < 4; i++) {
                int lin = tid + i * 256;
                int r = lin >> 4, c8 = (lin & 15) * 8;
                cp16(sB + (uint32_t)(r * 288 + c8 * 2),
                     Bm + (size_t)(c * 64 + r) * N_ + n0 + c8);
            }
        }
    };

    auto compute = [&](int s) {
        const __half* hA = reinterpret_cast<const __half*>(smem + (size_t)s * STAGE);
        const __half* hB = reinterpret_cast<const __half*>(smem + (size_t)s * STAGE + 20480);
#pragma unroll
        for (int ko = 0; ko < 4; ko++) {
            wmma::fragment<wmma::matrix_a, 16, 16, 16, __half, wmma::row_major> af[4];
#pragma unroll
            for (int i = 0; i < 4; i++)
                wmma::load_matrix_sync(af[i], hA + (mw + i * 16) * LDA + ko * 16, LDA);
            if (BTRANS) {
                wmma::fragment<wmma::matrix_b, 16, 16, 16, __half, wmma::col_major> bf[2];
#pragma unroll
                for (int j = 0; j < 2; j++)
                    wmma::load_matrix_sync(bf[j], hB + (nw + j * 16) * LDA + ko * 16, LDA);
#pragma unroll
                for (int i = 0; i < 4; i++)
#pragma unroll
                    for (int j = 0; j < 2; j++)
                        wmma::mma_sync(acc[i][j], af[i], bf[j], acc[i][j]);
            } else {
                wmma::fragment<wmma::matrix_b, 16, 16, 16, __half, wmma::row_major> bf[2];
#pragma unroll
                for (int j = 0; j < 2; j++)
                    wmma::load_matrix_sync(bf[j], hB + (ko * 16) * LDBN + nw + j * 16, LDBN);
#pragma unroll
                for (int i = 0; i < 4; i++)
#pragma unroll
                    for (int j = 0; j < 2; j++)
                        wmma::mma_sync(acc[i][j], af[i], bf[j], acc[i][j]);
            }
        }
    };

    // Prologue: stages 0,1
    load_chunk(0, 0);
    asm volatile("cp.async.commit_group;" ::: "memory");
    load_chunk(1, 1);
    asm volatile("cp.async.commit_group;" ::: "memory");

    for (int c = 0; c < nch; c++) {
        asm volatile("cp.async.wait_group 1;" ::: "memory");
        __syncthreads();                 // stage c%3 resident, stage (c+2)%3 free
        if (c + 2 < nch) load_chunk(c + 2, (c + 2) % 3);
        asm volatile("cp.async.commit_group;" ::: "memory");
        compute(c % 3);
    }
    __syncthreads();                     // all mma reads done; smem reusable

    // Epilogue: per-warp 16x16 staging in stage-0 smem.
    float* stg = reinterpret_cast<float*>(smem) + wid * 16 * 20;
#pragma unroll
    for (int i = 0; i < 4; i++) {
#pragma unroll
        for (int j = 0; j < 2; j++) {
            wmma::store_matrix_sync(stg, acc[i][j], 20, wmma::mem_row_major);
            __syncwarp();
#pragma unroll
            for (int l = 0; l < 8; l++) {
                const int e = lane + l * 32;
                const int r = e >> 4, cc = e & 15;
                const int col = n0 + nw + j * 16 + cc;
                const size_t idx = (size_t)blockIdx.z * strC +
                                   (size_t)(m0 + mw + i * 16 + r) * N_ + col;
                float v = stg[r * 20 + cc] * scale;
                if (bias) v += bias[col];
                if (OUTH) ((__half*)Cv)[idx] = __float2half_rn(v);
                else      ((float*)Cv)[idx] = v;
            }
            __syncwarp();
        }
    }
}

// ---------------------------------------------------------------------------
// fp32 -> fp16 conversion (vectorized)
// ---------------------------------------------------------------------------
__global__ void __launch_bounds__(256) f2h(const float* __restrict__ in,
                                           __half* __restrict__ out, int n4)
{
    int i = blockIdx.x * blockDim.x + threadIdx.x;
    if (i < n4) {
        float4 v = reinterpret_cast<const float4*>(in)[i];
        __half2 h0 = __floats2half2_rn(v.x, v.y);
        __half2 h1 = __floats2half2_rn(v.z, v.w);
        uint2 u;
        u.x = *reinterpret_cast<uint32_t*>(&h0);
        u.y = *reinterpret_cast<uint32_t*>(&h1);
        reinterpret_cast<uint2*>(out)[i] = u;
    }
}

// ---------------------------------------------------------------------------
// Row softmax over 2048 cols: fp32 logits in, fp16 probs out.
// ---------------------------------------------------------------------------
__global__ void __launch_bounds__(256) softmax2048(const float* __restrict__ A,
                                                   __half* __restrict__ P)
{
    const float* row = A + (size_t)blockIdx.x * 2048;
    __half* prow = P + (size_t)blockIdx.x * 2048;
    const int tid = threadIdx.x;
    const int lane = tid & 31, wid = tid >> 5;
    __shared__ float redm[8];
    __shared__ float reds[8];

    float v[8];
    float mx = -3.4e38f;
#pragma unroll
    for (int i = 0; i < 8; i++) { v[i] = row[tid + i * 256]; mx = fmaxf(mx, v[i]); }
#pragma unroll
    for (int o = 16; o; o >>= 1) mx = fmaxf(mx, __shfl_xor_sync(0xffffffffu, mx, o));
    if (lane == 0) redm[wid] = mx;
    __syncthreads();
    float m = redm[0];
#pragma unroll
    for (int i = 1; i < 8; i++) m = fmaxf(m, redm[i]);

    float s = 0.0f;
#pragma unroll
    for (int i = 0; i < 8; i++) { v[i] = __expf(v[i] - m); s += v[i]; }
#pragma unroll
    for (int o = 16; o; o >>= 1) s += __shfl_xor_sync(0xffffffffu, s, o);
    if (lane == 0) reds[wid] = s;
    __syncthreads();
    float t = 0.0f;
#pragma unroll
    for (int i = 0; i < 8; i++) t += reds[i];
    const float inv = 1.0f / t;
#pragma unroll
    for (int i = 0; i < 8; i++)
        prow[tid + i * 256] = __float2half_rn(v[i] * inv);
}

// ---------------------------------------------------------------------------
// kernel_launch
// ---------------------------------------------------------------------------
extern "C" void kernel_launch(void* const* d_in, const int* in_sizes, int n_in,
                              void* d_out, int out_size)
{
    (void)in_sizes; (void)n_in; (void)out_size;
    const float* X  = (const float*)d_in[0];
    const float* Wq = (const float*)d_in[1];
    const float* Wk = (const float*)d_in[2];
    const float* Wv = (const float*)d_in[3];
    const float* bq = (const float*)d_in[4];
    const float* bk = (const float*)d_in[5];
    const float* bv = (const float*)d_in[6];
    float* O = (float*)d_out;

    __half *Xh, *Wh, *Qh, *Kh, *Vh, *P;
    float *S;
    cudaGetSymbolAddress((void**)&Xh, g_Xh);
    cudaGetSymbolAddress((void**)&Wh, g_Wh);
    cudaGetSymbolAddress((void**)&Qh, g_Qh);
    cudaGetSymbolAddress((void**)&Kh, g_Kh);
    cudaGetSymbolAddress((void**)&Vh, g_Vh);
    cudaGetSymbolAddress((void**)&S,  g_S);
    cudaGetSymbolAddress((void**)&P,  g_P);

    cudaFuncSetAttribute(gemm_h<false, true>,  cudaFuncAttributeMaxDynamicSharedMemorySize, SMEM_TOTAL);
    cudaFuncSetAttribute(gemm_h<true,  false>, cudaFuncAttributeMaxDynamicSharedMemorySize, SMEM_TOTAL);
    cudaFuncSetAttribute(gemm_h<false, false>, cudaFuncAttributeMaxDynamicSharedMemorySize, SMEM_TOTAL);

    const size_t sQK = (size_t)2048 * 1024;
    const size_t sSS = (size_t)2048 * 2048;
    const size_t nW  = (size_t)1024 * 1024;

    // fp16 operand streams
    f2h<<<8192, 256>>>(X, Xh, 8192 * 1024 / 4);
    f2h<<<1024, 256>>>(Wq, Wh + 0 * nW, 1024 * 1024 / 4);
    f2h<<<1024, 256>>>(Wk, Wh + 1 * nW, 1024 * 1024 / 4);
    f2h<<<1024, 256>>>(Wv, Wh + 2 * nW, 1024 * 1024 / 4);

    // Projections: Qh/Kh/Vh[8192,1024] fp16 = Xh @ Wh + b
    dim3 gproj(8, 64, 1);
    gemm_h<false, true><<<gproj, 256, SMEM_TOTAL>>>(Xh, Wh + 0 * nW, bq, Qh, 1024, 1024, 0, 0, 0, 1.0f);
    gemm_h<false, true><<<gproj, 256, SMEM_TOTAL>>>(Xh, Wh + 1 * nW, bk, Kh, 1024, 1024, 0, 0, 0, 1.0f);
    gemm_h<false, true><<<gproj, 256, SMEM_TOTAL>>>(Xh, Wh + 2 * nW, bv, Vh, 1024, 1024, 0, 0, 0, 1.0f);

    // Logits fp32: S[b] = (Qh[b] @ Kh[b]^T) / 32
    dim3 glog(16, 16, 4);
    gemm_h<true, false><<<glog, 256, SMEM_TOTAL>>>(Qh, Kh, nullptr, S, 2048, 1024,
                                                   sQK, sQK, sSS, 0.03125f);

    // Softmax: fp32 logits -> fp16 probs
    softmax2048<<<4 * 2048, 256>>>(S, P);

    // Output fp32: O[b] = P[b] @ Vh[b]
    dim3 gout(8, 16, 4);
    gemm_h<false, false><<<gout, 256, SMEM_TOTAL>>>(P, Vh, nullptr, O, 1024, 2048,
                                                    sSS, sQK, sQK, 1.0f);
}

// round 7
// speedup vs baseline: 4.3791x; 1.2747x over previous
#include <cuda_runtime.h>
#include <cuda_fp16.h>
#include <mma.h>
#include <cstdint>
#include <cstddef>

using namespace nvcuda;

// B=4, S=2048, D=DK=DV=1024. Scratch: __device__ globals only.
__device__ __half g_Xh[(size_t)8192 * 1024];          // fp16 X
__device__ __half g_Wh[(size_t)3 * 1024 * 1024];      // fp16 Wq|Wk|Wv
__device__ __half g_Qh[(size_t)8192 * 1024];
__device__ __half g_Kh[(size_t)8192 * 1024];
__device__ __half g_Vh[(size_t)8192 * 1024];
__device__ __half g_S [(size_t)4 * 2048 * 2048];      // logits fp16
__device__ __half g_P [(size_t)4 * 2048 * 2048];      // probs fp16

__device__ __forceinline__ void cp16(uint32_t dst, const void* src) {
    asm volatile("cp.async.cg.shared.global [%0], [%1], 16;"
                 :: "r"(dst), "l"(src) : "memory");
}
__device__ __forceinline__ uint32_t smem_u32(const void* p) {
    uint32_t a;
    asm("{ .reg .u64 t; cvta.to.shared.u64 t, %1; cvt.u32.u64 %0, t; }"
        : "=r"(a) : "l"(p));
    return a;
}

// ---------------------------------------------------------------------------
// fp16 wmma GEMM, 128x128 CTA tile, BK=64, 3-stage cp.async pipeline.
//   BTRANS=true : B is [N,K] row-major -> C = A @ B^T
//   BTRANS=false: B is [K,N] row-major -> C = A @ B
//   OUTH: write __half C, else float C. scale applied, bias optional.
// Row strides chosen so (stride mod 128B)=16B -> conflict-free fragment loads:
//   A / B-trans rows: 72 halves (144 B);  B non-trans rows: 136 halves (272 B).
// Stage: A 128*144=18432 B + B max(128*144? no: trans 128*144, non-trans
// 64*272=17408) -> 18432+18432=36864 B. 3 stages = 110592 B -> 2 CTAs/SM.
// ---------------------------------------------------------------------------
constexpr int LDA   = 72;     // halves, A and B-trans smem rows (144 B)
constexpr int LDBN  = 136;    // halves, B non-trans smem rows (272 B)
constexpr int STAGE = 36864;  // bytes per stage
constexpr int SMEM_TOTAL = 3 * STAGE;  // 110592

template <bool BTRANS, bool OUTH>
__global__ void __launch_bounds__(256, 2) gemm_h(
    const __half* __restrict__ A, const __half* __restrict__ Bm,
    const float* __restrict__ bias, void* __restrict__ Cv,
    int N_, int K, size_t strA, size_t strB, size_t strC, float scale)
{
    extern __shared__ char smem[];
    const uint32_t sbase = smem_u32(smem);
    const int tid = threadIdx.x, wid = tid >> 5, lane = tid & 31;

    A  += (size_t)blockIdx.z * strA;
    Bm += (size_t)blockIdx.z * strB;
    const int m0 = blockIdx.y * 128;
    const int n0 = blockIdx.x * 128;
    const int mw = (wid >> 2) * 64;
    const int nw = (wid & 3) * 32;
    const int nch = K >> 6;

    wmma::fragment<wmma::accumulator, 16, 16, 16, float> acc[4][2];
#pragma unroll
    for (int i = 0; i < 4; i++)
#pragma unroll
        for (int j = 0; j < 2; j++) wmma::fill_fragment(acc[i][j], 0.0f);

    auto load_chunk = [&](int c, int s) {
        const uint32_t sA = sbase + (uint32_t)s * STAGE;
        const uint32_t sB = sA + 18432u;
#pragma unroll
        for (int i = 0; i < 4; i++) {                 // A: 128 rows x 64 halves
            int lin = tid + i * 256;
            int r = lin >> 3, c8 = (lin & 7) * 8;
            cp16(sA + (uint32_t)(r * 144 + c8 * 2),
                 A + (size_t)(m0 + r) * K + c * 64 + c8);
        }
        if (BTRANS) {                                 // B: 128 rows x 64 halves
#pragma unroll
            for (int i = 0; i < 4; i++) {
                int lin = tid + i * 256;
                int r = lin >> 3, c8 = (lin & 7) * 8;
                cp16(sB + (uint32_t)(r * 144 + c8 * 2),
                     Bm + (size_t)(n0 + r) * K + c * 64 + c8);
            }
        } else {                                      // B: 64 rows x 128 halves
#pragma unroll
            for (int i = 0; i < 4; i++) {
                int lin = tid + i * 256;
                int r = lin >> 4, c8 = (lin & 15) * 8;
                cp16(sB + (uint32_t)(r * 272 + c8 * 2),
                     Bm + (size_t)(c * 64 + r) * N_ + n0 + c8);
            }
        }
    };

    auto compute = [&](int s) {
        const __half* hA = reinterpret_cast<const __half*>(smem + (size_t)s * STAGE);
        const __half* hB = reinterpret_cast<const __half*>(smem + (size_t)s * STAGE + 18432);
#pragma unroll
        for (int ko = 0; ko < 4; ko++) {
            wmma::fragment<wmma::matrix_a, 16, 16, 16, __half, wmma::row_major> af[4];
#pragma unroll
            for (int i = 0; i < 4; i++)
                wmma::load_matrix_sync(af[i], hA + (mw + i * 16) * LDA + ko * 16, LDA);
            if (BTRANS) {
                wmma::fragment<wmma::matrix_b, 16, 16, 16, __half, wmma::col_major> bf[2];
#pragma unroll
                for (int j = 0; j < 2; j++)
                    wmma::load_matrix_sync(bf[j], hB + (nw + j * 16) * LDA + ko * 16, LDA);
#pragma unroll
                for (int i = 0; i < 4; i++)
#pragma unroll
                    for (int j = 0; j < 2; j++)
                        wmma::mma_sync(acc[i][j], af[i], bf[j], acc[i][j]);
            } else {
                wmma::fragment<wmma::matrix_b, 16, 16, 16, __half, wmma::row_major> bf[2];
#pragma unroll
                for (int j = 0; j < 2; j++)
                    wmma::load_matrix_sync(bf[j], hB + (ko * 16) * LDBN + nw + j * 16, LDBN);
#pragma unroll
                for (int i = 0; i < 4; i++)
#pragma unroll
                    for (int j = 0; j < 2; j++)
                        wmma::mma_sync(acc[i][j], af[i], bf[j], acc[i][j]);
            }
        }
    };

    // Prologue: stages 0,1
    load_chunk(0, 0);
    asm volatile("cp.async.commit_group;" ::: "memory");
    load_chunk(1, 1);
    asm volatile("cp.async.commit_group;" ::: "memory");

    for (int c = 0; c < nch; c++) {
        asm volatile("cp.async.wait_group 1;" ::: "memory");
        __syncthreads();                 // stage c%3 resident, stage (c+2)%3 free
        if (c + 2 < nch) load_chunk(c + 2, (c + 2) % 3);
        asm volatile("cp.async.commit_group;" ::: "memory");
        compute(c % 3);
    }
    __syncthreads();                     // all mma reads done; smem reusable

    // Epilogue: per-warp 16x16 staging in stage-0 smem.
    float* stg = reinterpret_cast<float*>(smem) + wid * 16 * 20;
#pragma unroll
    for (int i = 0; i < 4; i++) {
#pragma unroll
        for (int j = 0; j < 2; j++) {
            wmma::store_matrix_sync(stg, acc[i][j], 20, wmma::mem_row_major);
            __syncwarp();
#pragma unroll
            for (int l = 0; l < 8; l++) {
                const int e = lane + l * 32;
                const int r = e >> 4, cc = e & 15;
                const int col = n0 + nw + j * 16 + cc;
                const size_t idx = (size_t)blockIdx.z * strC +
                                   (size_t)(m0 + mw + i * 16 + r) * N_ + col;
                float v = stg[r * 20 + cc] * scale;
                if (bias) v += bias[col];
                if (OUTH) ((__half*)Cv)[idx] = __float2half_rn(v);
                else      ((float*)Cv)[idx] = v;
            }
            __syncwarp();
        }
    }
}

// ---------------------------------------------------------------------------
// fp32 -> fp16 conversion (vectorized)
// ---------------------------------------------------------------------------
__global__ void __launch_bounds__(256) f2h(const float* __restrict__ in,
                                           __half* __restrict__ out, int n4)
{
    int i = blockIdx.x * blockDim.x + threadIdx.x;
    if (i < n4) {
        float4 v = reinterpret_cast<const float4*>(in)[i];
        __half2 h0 = __floats2half2_rn(v.x, v.y);
        __half2 h1 = __floats2half2_rn(v.z, v.w);
        uint2 u;
        u.x = *reinterpret_cast<uint32_t*>(&h0);
        u.y = *reinterpret_cast<uint32_t*>(&h1);
        reinterpret_cast<uint2*>(out)[i] = u;
    }
}

// ---------------------------------------------------------------------------
// Row softmax over 2048 cols: fp16 logits in, fp16 probs out (fp32 math).
// ---------------------------------------------------------------------------
__global__ void __launch_bounds__(256) softmax2048(const __half* __restrict__ A,
                                                   __half* __restrict__ P)
{
    const __half2* row = reinterpret_cast<const __half2*>(A + (size_t)blockIdx.x * 2048);
    __half2* prow = reinterpret_cast<__half2*>(P + (size_t)blockIdx.x * 2048);
    const int tid = threadIdx.x;
    const int lane = tid & 31, wid = tid >> 5;
    __shared__ float redm[8];
    __shared__ float reds[8];

    float2 v[4];
    float mx = -3.4e38f;
#pragma unroll
    for (int i = 0; i < 4; i++) {
        v[i] = __half22float2(row[tid + i * 256]);
        mx = fmaxf(mx, fmaxf(v[i].x, v[i].y));
    }
#pragma unroll
    for (int o = 16; o; o >>= 1) mx = fmaxf(mx, __shfl_xor_sync(0xffffffffu, mx, o));
    if (lane == 0) redm[wid] = mx;
    __syncthreads();
    float m = redm[0];
#pragma unroll
    for (int i = 1; i < 8; i++) m = fmaxf(m, redm[i]);

    float s = 0.0f;
#pragma unroll
    for (int i = 0; i < 4; i++) {
        v[i].x = __expf(v[i].x - m);
        v[i].y = __expf(v[i].y - m);
        s += v[i].x + v[i].y;
    }
#pragma unroll
    for (int o = 16; o; o >>= 1) s += __shfl_xor_sync(0xffffffffu, s, o);
    if (lane == 0) reds[wid] = s;
    __syncthreads();
    float t = 0.0f;
#pragma unroll
    for (int i = 0; i < 8; i++) t += reds[i];
    const float inv = 1.0f / t;
#pragma unroll
    for (int i = 0; i < 4; i++)
        prow[tid + i * 256] = __floats2half2_rn(v[i].x * inv, v[i].y * inv);
}

// ---------------------------------------------------------------------------
// kernel_launch
// ---------------------------------------------------------------------------
extern "C" void kernel_launch(void* const* d_in, const int* in_sizes, int n_in,
                              void* d_out, int out_size)
{
    (void)in_sizes; (void)n_in; (void)out_size;
    const float* X  = (const float*)d_in[0];
    const float* Wq = (const float*)d_in[1];
    const float* Wk = (const float*)d_in[2];
    const float* Wv = (const float*)d_in[3];
    const float* bq = (const float*)d_in[4];
    const float* bk = (const float*)d_in[5];
    const float* bv = (const float*)d_in[6];
    float* O = (float*)d_out;

    __half *Xh, *Wh, *Qh, *Kh, *Vh, *S, *P;
    cudaGetSymbolAddress((void**)&Xh, g_Xh);
    cudaGetSymbolAddress((void**)&Wh, g_Wh);
    cudaGetSymbolAddress((void**)&Qh, g_Qh);
    cudaGetSymbolAddress((void**)&Kh, g_Kh);
    cudaGetSymbolAddress((void**)&Vh, g_Vh);
    cudaGetSymbolAddress((void**)&S,  g_S);
    cudaGetSymbolAddress((void**)&P,  g_P);

    cudaFuncSetAttribute(gemm_h<false, true>,  cudaFuncAttributeMaxDynamicSharedMemorySize, SMEM_TOTAL);
    cudaFuncSetAttribute(gemm_h<true,  true>,  cudaFuncAttributeMaxDynamicSharedMemorySize, SMEM_TOTAL);
    cudaFuncSetAttribute(gemm_h<false, false>, cudaFuncAttributeMaxDynamicSharedMemorySize, SMEM_TOTAL);

    const size_t sQK = (size_t)2048 * 1024;
    const size_t sSS = (size_t)2048 * 2048;
    const size_t nW  = (size_t)1024 * 1024;

    // fp16 operand streams
    f2h<<<8192, 256>>>(X, Xh, 8192 * 1024 / 4);
    f2h<<<1024, 256>>>(Wq, Wh + 0 * nW, 1024 * 1024 / 4);
    f2h<<<1024, 256>>>(Wk, Wh + 1 * nW, 1024 * 1024 / 4);
    f2h<<<1024, 256>>>(Wv, Wh + 2 * nW, 1024 * 1024 / 4);

    // Projections: Qh/Kh/Vh[8192,1024] fp16 = Xh @ Wh + b
    dim3 gproj(8, 64, 1);
    gemm_h<false, true><<<gproj, 256, SMEM_TOTAL>>>(Xh, Wh + 0 * nW, bq, Qh, 1024, 1024, 0, 0, 0, 1.0f);
    gemm_h<false, true><<<gproj, 256, SMEM_TOTAL>>>(Xh, Wh + 1 * nW, bk, Kh, 1024, 1024, 0, 0, 0, 1.0f);
    gemm_h<false, true><<<gproj, 256, SMEM_TOTAL>>>(Xh, Wh + 2 * nW, bv, Vh, 1024, 1024, 0, 0, 0, 1.0f);

    // Logits fp16: S[b] = (Qh[b] @ Kh[b]^T) / 32
    dim3 glog(16, 16, 4);
    gemm_h<true, true><<<glog, 256, SMEM_TOTAL>>>(Qh, Kh, nullptr, S, 2048, 1024,
                                                  sQK, sQK, sSS, 0.03125f);

    // Softmax: fp16 logits -> fp16 probs
    softmax2048<<<4 * 2048, 256>>>(S, P);

    // Output fp32: O[b] = P[b] @ Vh[b]
    dim3 gout(8, 16, 4);
    gemm_h<false, false><<<gout, 256, SMEM_TOTAL>>>(P, Vh, nullptr, O, 1024, 2048,
                                                    sSS, sQK, sQK, 1.0f);
}

// round 9
// speedup vs baseline: 4.5255x; 1.0334x over previous
#include <cuda_runtime.h>
#include <cuda_fp16.h>
#include <mma.h>
#include <cstdint>
#include <cstddef>

using namespace nvcuda;

// B=4, S=2048, D=DK=DV=1024. Scratch: __device__ globals only.
__device__ __half g_Xh  [(size_t)8192 * 1024];         // fp16 X
__device__ __half g_Wh  [(size_t)3 * 1024 * 1024];     // fp16 Wq|Wk|Wv contiguous
__device__ __half g_QKV [(size_t)3 * 8192 * 1024];     // fp16 Q|K|V contiguous
__device__ __half g_P   [(size_t)4 * 2048 * 2048];     // exp(logit-4) fp16
__device__ float  g_R   [8192];                        // per-row 1/sum

__device__ __forceinline__ void cp16(uint32_t dst, const void* src) {
    asm volatile("cp.async.cg.shared.global [%0], [%1], 16;"
                 :: "r"(dst), "l"(src) : "memory");
}
__device__ __forceinline__ uint32_t smem_u32(const void* p) {
    uint32_t a;
    asm("{ .reg .u64 t; cvta.to.shared.u64 t, %1; cvt.u32.u64 %0, t; }"
        : "=r"(a) : "l"(p));
    return a;
}

// ---------------------------------------------------------------------------
// fp16 wmma GEMM, 128x128 CTA tile, BK=64, 3-stage cp.async pipeline.
// BT=1: B is [N,K] row-major (C = A @ B^T); BT=0: B is [K,N] row-major.
// MODE 0: fused QKV projection. Grid.x=24: w=x>>3 selects W/bias/out.
//         out = half(v + bias[col]).
// MODE 1: out = half(exp(v*scale - 4))   (logits -> unnormalized probs)
// MODE 2: out = float(v * rowinv[row])   (AV, normalized)
// Row strides: A/B-trans 72 halves (144 B ≡ 16 mod 128 -> conflict-free),
// B non-trans 136 halves (272 B ≡ 16 mod 128).
// ---------------------------------------------------------------------------
constexpr int LDA   = 72;
constexpr int LDBN  = 136;
constexpr int STAGE = 36864;
constexpr int SMEM_TOTAL = 3 * STAGE;  // 110592 -> 2 CTAs/SM

template <int BT, int MODE>
__global__ void __launch_bounds__(256, 2) gemm_h(
    const __half* __restrict__ A, const __half* __restrict__ Bm,
    const float* __restrict__ bq, const float* __restrict__ bk,
    const float* __restrict__ bv, const float* __restrict__ rowinv,
    void* __restrict__ Cv,
    int N_, int K, size_t strA, size_t strB, size_t strC, float scale)
{
    extern __shared__ char smem[];
    const uint32_t sbase = smem_u32(smem);
    const int tid = threadIdx.x, wid = tid >> 5, lane = tid & 31;

    const float* bias = nullptr;
    int n0;
    if (MODE == 0) {
        const int w = blockIdx.x >> 3;
        n0 = (blockIdx.x & 7) * 128;
        Bm += (size_t)w * 1048576;                    // w-th weight matrix
        Cv = (void*)((__half*)Cv + (size_t)w * 8388608);
        bias = (w == 0) ? bq : (w == 1) ? bk : bv;
    } else {
        n0 = blockIdx.x * 128;
        A  += (size_t)blockIdx.z * strA;
        Bm += (size_t)blockIdx.z * strB;
    }
    const int m0 = blockIdx.y * 128;
    const int mw = (wid >> 2) * 64;
    const int nw = (wid & 3) * 32;
    const int nch = K >> 6;

    wmma::fragment<wmma::accumulator, 16, 16, 16, float> acc[4][2];
#pragma unroll
    for (int i = 0; i < 4; i++)
#pragma unroll
        for (int j = 0; j < 2; j++) wmma::fill_fragment(acc[i][j], 0.0f);

    auto load_chunk = [&](int c, int s) {
        const uint32_t sA = sbase + (uint32_t)s * STAGE;
        const uint32_t sB = sA + 18432u;
#pragma unroll
        for (int i = 0; i < 4; i++) {                 // A: 128 rows x 64 halves
            int lin = tid + i * 256;
            int r = lin >> 3, c8 = (lin & 7) * 8;
            cp16(sA + (uint32_t)(r * 144 + c8 * 2),
                 A + (size_t)(m0 + r) * K + c * 64 + c8);
        }
        if (BT) {                                     // B: 128 rows x 64 halves
#pragma unroll
            for (int i = 0; i < 4; i++) {
                int lin = tid + i * 256;
                int r = lin >> 3, c8 = (lin & 7) * 8;
                cp16(sB + (uint32_t)(r * 144 + c8 * 2),
                     Bm + (size_t)(n0 + r) * K + c * 64 + c8);
            }
        } else {                                      // B: 64 rows x 128 halves
#pragma unroll
            for (int i = 0; i < 4; i++) {
                int lin = tid + i * 256;
                int r = lin >> 4, c8 = (lin & 15) * 8;
                cp16(sB + (uint32_t)(r * 272 + c8 * 2),
                     Bm + (size_t)(c * 64 + r) * N_ + n0 + c8);
            }
        }
    };

    auto compute = [&](int s) {
        const __half* hA = reinterpret_cast<const __half*>(smem + (size_t)s * STAGE);
        const __half* hB = reinterpret_cast<const __half*>(smem + (size_t)s * STAGE + 18432);
#pragma unroll
        for (int ko = 0; ko < 4; ko++) {
            wmma::fragment<wmma::matrix_a, 16, 16, 16, __half, wmma::row_major> af[4];
#pragma unroll
            for (int i = 0; i < 4; i++)
                wmma::load_matrix_sync(af[i], hA + (mw + i * 16) * LDA + ko * 16, LDA);
            if (BT) {
                wmma::fragment<wmma::matrix_b, 16, 16, 16, __half, wmma::col_major> bf[2];
#pragma unroll
                for (int j = 0; j < 2; j++)
                    wmma::load_matrix_sync(bf[j], hB + (nw + j * 16) * LDA + ko * 16, LDA);
#pragma unroll
                for (int i = 0; i < 4; i++)
#pragma unroll
                    for (int j = 0; j < 2; j++)
                        wmma::mma_sync(acc[i][j], af[i], bf[j], acc[i][j]);
            } else {
                wmma::fragment<wmma::matrix_b, 16, 16, 16, __half, wmma::row_major> bf[2];
#pragma unroll
                for (int j = 0; j < 2; j++)
                    wmma::load_matrix_sync(bf[j], hB + (ko * 16) * LDBN + nw + j * 16, LDBN);
#pragma unroll
                for (int i = 0; i < 4; i++)
#pragma unroll
                    for (int j = 0; j < 2; j++)
                        wmma::mma_sync(acc[i][j], af[i], bf[j], acc[i][j]);
            }
        }
    };

    load_chunk(0, 0);
    asm volatile("cp.async.commit_group;" ::: "memory");
    load_chunk(1, 1);
    asm volatile("cp.async.commit_group;" ::: "memory");

    for (int c = 0; c < nch; c++) {
        asm volatile("cp.async.wait_group 1;" ::: "memory");
        __syncthreads();
        if (c + 2 < nch) load_chunk(c + 2, (c + 2) % 3);
        asm volatile("cp.async.commit_group;" ::: "memory");
        compute(c % 3);
    }
    __syncthreads();

    // Epilogue: per-warp 16x16 staging.
    float* stg = reinterpret_cast<float*>(smem) + wid * 16 * 20;
#pragma unroll
    for (int i = 0; i < 4; i++) {
#pragma unroll
        for (int j = 0; j < 2; j++) {
            wmma::store_matrix_sync(stg, acc[i][j], 20, wmma::mem_row_major);
            __syncwarp();
#pragma unroll
            for (int l = 0; l < 8; l++) {
                const int e = lane + l * 32;
                const int r = e >> 4, cc = e & 15;
                const int row = m0 + mw + i * 16 + r;
                const int col = n0 + nw + j * 16 + cc;
                const size_t idx = (size_t)blockIdx.z * strC + (size_t)row * N_ + col;
                float v = stg[r * 20 + cc];
                if (MODE == 0) {
                    ((__half*)Cv)[idx] = __float2half_rn(v + bias[col]);
                } else if (MODE == 1) {
                    ((__half*)Cv)[idx] = __float2half_rn(__expf(v * scale - 4.0f));
                } else {
                    ((float*)Cv)[idx] = v * rowinv[blockIdx.z * 2048 + row];
                }
            }
            __syncwarp();
        }
    }
}

// ---------------------------------------------------------------------------
// fp32 -> fp16 conversion (vectorized)
// ---------------------------------------------------------------------------
__global__ void __launch_bounds__(256) f2h(const float* __restrict__ in,
                                           __half* __restrict__ out, int n4)
{
    int i = blockIdx.x * blockDim.x + threadIdx.x;
    if (i < n4) {
        float4 v = reinterpret_cast<const float4*>(in)[i];
        __half2 h0 = __floats2half2_rn(v.x, v.y);
        __half2 h1 = __floats2half2_rn(v.z, v.w);
        uint2 u;
        u.x = *reinterpret_cast<uint32_t*>(&h0);
        u.y = *reinterpret_cast<uint32_t*>(&h1);
        reinterpret_cast<uint2*>(out)[i] = u;
    }
}

// ---------------------------------------------------------------------------
// Per-row inverse sums: one warp per row (2048 fp16 -> fp32 sum -> 1/sum).
// ---------------------------------------------------------------------------
__global__ void __launch_bounds__(256) rowinv2048(const __half* __restrict__ P,
                                                  float* __restrict__ R)
{
    const int wid = threadIdx.x >> 5, lane = threadIdx.x & 31;
    const int row = blockIdx.x * 8 + wid;
    const uint4* src = reinterpret_cast<const uint4*>(P + (size_t)row * 2048);

    float s = 0.0f;
#pragma unroll
    for (int it = 0; it < 8; it++) {
        uint4 u = src[lane + it * 32];
#pragma unroll
        for (int q = 0; q < 4; q++) {
            uint32_t w = (q == 0) ? u.x : (q == 1) ? u.y : (q == 2) ? u.z : u.w;
            float2 f = __half22float2(*reinterpret_cast<__half2*>(&w));
            s += f.x + f.y;
        }
    }
#pragma unroll
    for (int o = 16; o; o >>= 1) s += __shfl_xor_sync(0xffffffffu, s, o);
    if (lane == 0) R[row] = 1.0f / s;
}

// ---------------------------------------------------------------------------
// kernel_launch
// ---------------------------------------------------------------------------
extern "C" void kernel_launch(void* const* d_in, const int* in_sizes, int n_in,
                              void* d_out, int out_size)
{
    (void)in_sizes; (void)n_in; (void)out_size;
    const float* X  = (const float*)d_in[0];
    const float* Wq = (const float*)d_in[1];
    const float* Wk = (const float*)d_in[2];
    const float* Wv = (const float*)d_in[3];
    const float* bq = (const float*)d_in[4];
    const float* bk = (const float*)d_in[5];
    const float* bv = (const float*)d_in[6];
    float* O = (float*)d_out;

    __half *Xh, *Wh, *QKV, *P;
    float *R;
    cudaGetSymbolAddress((void**)&Xh,  g_Xh);
    cudaGetSymbolAddress((void**)&Wh,  g_Wh);
    cudaGetSymbolAddress((void**)&QKV, g_QKV);
    cudaGetSymbolAddress((void**)&P,   g_P);
    cudaGetSymbolAddress((void**)&R,   g_R);

    cudaFuncSetAttribute(gemm_h<0, 0>, cudaFuncAttributeMaxDynamicSharedMemorySize, SMEM_TOTAL);
    cudaFuncSetAttribute(gemm_h<1, 1>, cudaFuncAttributeMaxDynamicSharedMemorySize, SMEM_TOTAL);
    cudaFuncSetAttribute(gemm_h<0, 2>, cudaFuncAttributeMaxDynamicSharedMemorySize, SMEM_TOTAL);

    const size_t sQK = (size_t)2048 * 1024;
    const size_t sSS = (size_t)2048 * 2048;
    const size_t nW  = (size_t)1024 * 1024;

    __half* Qh = QKV;
    __half* Kh = QKV + (size_t)8192 * 1024;
    __half* Vh = QKV + (size_t)2 * 8192 * 1024;

    // fp16 operand streams
    f2h<<<8192, 256>>>(X, Xh, 8192 * 1024 / 4);
    f2h<<<1024, 256>>>(Wq, Wh + 0 * nW, 1024 * 1024 / 4);
    f2h<<<1024, 256>>>(Wk, Wh + 1 * nW, 1024 * 1024 / 4);
    f2h<<<1024, 256>>>(Wv, Wh + 2 * nW, 1024 * 1024 / 4);

    // Fused projections: one launch computes Q, K, V (+bias), fp16
    dim3 gproj(24, 64, 1);
    gemm_h<0, 0><<<gproj, 256, SMEM_TOTAL>>>(Xh, Wh, bq, bk, bv, nullptr, QKV,
                                             1024, 1024, 0, 0, 0, 1.0f);

    // Logits -> unnormalized probs: P[b] = exp(Qh Kh^T / 32 - 4), fp16
    dim3 glog(16, 16, 4);
    gemm_h<1, 1><<<glog, 256, SMEM_TOTAL>>>(Qh, Kh, nullptr, nullptr, nullptr,
                                            nullptr, P, 2048, 1024,
                                            sQK, sQK, sSS, 0.03125f);

    // Per-row 1/sum (deterministic warp reduction)
    rowinv2048<<<1024, 256>>>(P, R);

    // Output: O[b] = (P[b] @ V[b]) * rowinv, fp32
    dim3 gout(8, 16, 4);
    gemm_h<0, 2><<<gout, 256, SMEM_TOTAL>>>(P, Vh, nullptr, nullptr, nullptr,
                                            R, O, 1024, 2048,
                                            sSS, sQK, sQK, 1.0f);
}

// round 10
// speedup vs baseline: 4.5756x; 1.0111x over previous
#include <cuda_runtime.h>
#include <cuda_fp16.h>
#include <mma.h>
#include <cstdint>
#include <cstddef>

using namespace nvcuda;

// B=4, S=2048, D=DK=DV=1024. Scratch: __device__ globals only.
__device__ __half g_Xh  [(size_t)8192 * 1024];         // fp16 X
__device__ __half g_Wh  [(size_t)3 * 1024 * 1024];     // fp16 Wq|Wk|Wv contiguous
__device__ __half g_QKV [(size_t)3 * 8192 * 1024];     // fp16 Q|K|V contiguous
__device__ __half g_P   [(size_t)4 * 2048 * 2048];     // exp(logit-4) fp16
__device__ float  g_R   [8192];                        // per-row 1/sum

__device__ __forceinline__ void cp16(uint32_t dst, const void* src) {
    asm volatile("cp.async.cg.shared.global [%0], [%1], 16;"
                 :: "r"(dst), "l"(src) : "memory");
}
__device__ __forceinline__ uint32_t smem_u32(const void* p) {
    uint32_t a;
    asm("{ .reg .u64 t; cvta.to.shared.u64 t, %1; cvt.u32.u64 %0, t; }"
        : "=r"(a) : "l"(p));
    return a;
}

// ---------------------------------------------------------------------------
// fp16 wmma GEMM, 128x128 CTA tile, BK=64, 3-stage cp.async pipeline.
// BT=1: B is [N,K] row-major (C = A @ B^T); BT=0: B is [K,N] row-major.
// MODE 0: fused QKV projection (grid.x=24, w=x>>3): out = half(v + bias[col])
// MODE 1: out = half(exp(v*scale - 4))   (logits -> unnormalized probs)
// MODE 2: out = float(v * rowinv[row])   (AV, normalized)
// Row strides: A/B-trans 72 halves (144 B ≡ 16 mod 128 -> conflict-free),
// B non-trans 136 halves (272 B ≡ 16 mod 128).
// ---------------------------------------------------------------------------
constexpr int LDA   = 72;
constexpr int LDBN  = 136;
constexpr int STAGE = 36864;
constexpr int SMEM_TOTAL = 3 * STAGE;  // 110592 -> 2 CTAs/SM

template <int BT, int MODE>
__global__ void __launch_bounds__(256, 2) gemm_h(
    const __half* __restrict__ A, const __half* __restrict__ Bm,
    const float* __restrict__ bq, const float* __restrict__ bk,
    const float* __restrict__ bv, const float* __restrict__ rowinv,
    void* __restrict__ Cv,
    int N_, int K, size_t strA, size_t strB, size_t strC, float scale)
{
    extern __shared__ char smem[];
    const uint32_t sbase = smem_u32(smem);
    const int tid = threadIdx.x, wid = tid >> 5, lane = tid & 31;

    const float* bias = nullptr;
    int n0;
    if (MODE == 0) {
        const int w = blockIdx.x >> 3;
        n0 = (blockIdx.x & 7) * 128;
        Bm += (size_t)w * 1048576;                    // w-th weight matrix
        Cv = (void*)((__half*)Cv + (size_t)w * 8388608);
        bias = (w == 0) ? bq : (w == 1) ? bk : bv;
    } else {
        n0 = blockIdx.x * 128;
        A  += (size_t)blockIdx.z * strA;
        Bm += (size_t)blockIdx.z * strB;
    }
    const int m0 = blockIdx.y * 128;
    const int mw = (wid >> 2) * 64;
    const int nw = (wid & 3) * 32;
    const int nch = K >> 6;

    wmma::fragment<wmma::accumulator, 16, 16, 16, float> acc[4][2];
#pragma unroll
    for (int i = 0; i < 4; i++)
#pragma unroll
        for (int j = 0; j < 2; j++) wmma::fill_fragment(acc[i][j], 0.0f);

    auto load_chunk = [&](int c, int s) {
        const uint32_t sA = sbase + (uint32_t)s * STAGE;
        const uint32_t sB = sA + 18432u;
#pragma unroll
        for (int i = 0; i < 4; i++) {                 // A: 128 rows x 64 halves
            int lin = tid + i * 256;
            int r = lin >> 3, c8 = (lin & 7) * 8;
            cp16(sA + (uint32_t)(r * 144 + c8 * 2),
                 A + (size_t)(m0 + r) * K + c * 64 + c8);
        }
        if (BT) {                                     // B: 128 rows x 64 halves
#pragma unroll
            for (int i = 0; i < 4; i++) {
                int lin = tid + i * 256;
                int r = lin >> 3, c8 = (lin & 7) * 8;
                cp16(sB + (uint32_t)(r * 144 + c8 * 2),
                     Bm + (size_t)(n0 + r) * K + c * 64 + c8);
            }
        } else {                                      // B: 64 rows x 128 halves
#pragma unroll
            for (int i = 0; i < 4; i++) {
                int lin = tid + i * 256;
                int r = lin >> 4, c8 = (lin & 15) * 8;
                cp16(sB + (uint32_t)(r * 272 + c8 * 2),
                     Bm + (size_t)(c * 64 + r) * N_ + n0 + c8);
            }
        }
    };

    auto compute = [&](int s) {
        const __half* hA = reinterpret_cast<const __half*>(smem + (size_t)s * STAGE);
        const __half* hB = reinterpret_cast<const __half*>(smem + (size_t)s * STAGE + 18432);
#pragma unroll
        for (int ko = 0; ko < 4; ko++) {
            wmma::fragment<wmma::matrix_a, 16, 16, 16, __half, wmma::row_major> af[4];
#pragma unroll
            for (int i = 0; i < 4; i++)
                wmma::load_matrix_sync(af[i], hA + (mw + i * 16) * LDA + ko * 16, LDA);
            if (BT) {
                wmma::fragment<wmma::matrix_b, 16, 16, 16, __half, wmma::col_major> bf[2];
#pragma unroll
                for (int j = 0; j < 2; j++)
                    wmma::load_matrix_sync(bf[j], hB + (nw + j * 16) * LDA + ko * 16, LDA);
#pragma unroll
                for (int i = 0; i < 4; i++)
#pragma unroll
                    for (int j = 0; j < 2; j++)
                        wmma::mma_sync(acc[i][j], af[i], bf[j], acc[i][j]);
            } else {
                wmma::fragment<wmma::matrix_b, 16, 16, 16, __half, wmma::row_major> bf[2];
#pragma unroll
                for (int j = 0; j < 2; j++)
                    wmma::load_matrix_sync(bf[j], hB + (ko * 16) * LDBN + nw + j * 16, LDBN);
#pragma unroll
                for (int i = 0; i < 4; i++)
#pragma unroll
                    for (int j = 0; j < 2; j++)
                        wmma::mma_sync(acc[i][j], af[i], bf[j], acc[i][j]);
            }
        }
    };

    load_chunk(0, 0);
    asm volatile("cp.async.commit_group;" ::: "memory");
    load_chunk(1, 1);
    asm volatile("cp.async.commit_group;" ::: "memory");

    for (int c = 0; c < nch; c++) {
        asm volatile("cp.async.wait_group 1;" ::: "memory");
        __syncthreads();
        if (c + 2 < nch) load_chunk(c + 2, (c + 2) % 3);
        asm volatile("cp.async.commit_group;" ::: "memory");
        compute(c % 3);
    }
    __syncthreads();

    // Epilogue: per-warp 16x16 staging, vectorized 4-wide stores.
    // Items: 16 rows x 4 col-groups = 64; lane handles items lane, lane+32.
    float* stg = reinterpret_cast<float*>(smem) + wid * 16 * 20;
#pragma unroll
    for (int i = 0; i < 4; i++) {
#pragma unroll
        for (int j = 0; j < 2; j++) {
            wmma::store_matrix_sync(stg, acc[i][j], 20, wmma::mem_row_major);
            __syncwarp();
#pragma unroll
            for (int l = 0; l < 2; l++) {
                const int item = lane + l * 32;
                const int r = item >> 2, g = item & 3;
                const int row = m0 + mw + i * 16 + r;
                const int col = n0 + nw + j * 16 + g * 4;
                const size_t idx = (size_t)blockIdx.z * strC + (size_t)row * N_ + col;
                float4 v = *reinterpret_cast<const float4*>(&stg[r * 20 + g * 4]);
                if (MODE == 0) {
                    const float4 b4 = *reinterpret_cast<const float4*>(&bias[col]);
                    __half2 h0 = __floats2half2_rn(v.x + b4.x, v.y + b4.y);
                    __half2 h1 = __floats2half2_rn(v.z + b4.z, v.w + b4.w);
                    uint2 u = {*reinterpret_cast<uint32_t*>(&h0),
                               *reinterpret_cast<uint32_t*>(&h1)};
                    *reinterpret_cast<uint2*>((__half*)Cv + idx) = u;
                } else if (MODE == 1) {
                    __half2 h0 = __floats2half2_rn(__expf(v.x * scale - 4.0f),
                                                   __expf(v.y * scale - 4.0f));
                    __half2 h1 = __floats2half2_rn(__expf(v.z * scale - 4.0f),
                                                   __expf(v.w * scale - 4.0f));
                    uint2 u = {*reinterpret_cast<uint32_t*>(&h0),
                               *reinterpret_cast<uint32_t*>(&h1)};
                    *reinterpret_cast<uint2*>((__half*)Cv + idx) = u;
                } else {
                    const float rv = rowinv[blockIdx.z * 2048 + row];
                    v.x *= rv; v.y *= rv; v.z *= rv; v.w *= rv;
                    *reinterpret_cast<float4*>((float*)Cv + idx) = v;
                }
            }
            __syncwarp();
        }
    }
}

// ---------------------------------------------------------------------------
// fp32 -> fp16 conversion. grid.y selects among up to 3 source matrices
// (merged weight conversion); pass the same pointer 3x + ny=1 for X.
// ---------------------------------------------------------------------------
__global__ void __launch_bounds__(256) f2h3(const float* __restrict__ s0,
                                            const float* __restrict__ s1,
                                            const float* __restrict__ s2,
                                            __half* __restrict__ out,
                                            int n4_per)
{
    const int z = blockIdx.y;
    const float* in = (z == 0) ? s0 : (z == 1) ? s1 : s2;
    __half* dst = out + (size_t)z * n4_per * 4;
    int i = blockIdx.x * blockDim.x + threadIdx.x;
    if (i < n4_per) {
        float4 v = reinterpret_cast<const float4*>(in)[i];
        __half2 h0 = __floats2half2_rn(v.x, v.y);
        __half2 h1 = __floats2half2_rn(v.z, v.w);
        uint2 u;
        u.x = *reinterpret_cast<uint32_t*>(&h0);
        u.y = *reinterpret_cast<uint32_t*>(&h1);
        reinterpret_cast<uint2*>(dst)[i] = u;
    }
}

// ---------------------------------------------------------------------------
// Per-row inverse sums: one warp per row (2048 fp16 -> fp32 sum -> 1/sum).
// ---------------------------------------------------------------------------
__global__ void __launch_bounds__(256) rowinv2048(const __half* __restrict__ P,
                                                  float* __restrict__ R)
{
    const int wid = threadIdx.x >> 5, lane = threadIdx.x & 31;
    const int row = blockIdx.x * 8 + wid;
    const uint4* src = reinterpret_cast<const uint4*>(P + (size_t)row * 2048);

    float s = 0.0f;
#pragma unroll
    for (int it = 0; it < 8; it++) {
        uint4 u = src[lane + it * 32];
#pragma unroll
        for (int q = 0; q < 4; q++) {
            uint32_t w = (q == 0) ? u.x : (q == 1) ? u.y : (q == 2) ? u.z : u.w;
            float2 f = __half22float2(*reinterpret_cast<__half2*>(&w));
            s += f.x + f.y;
        }
    }
#pragma unroll
    for (int o = 16; o; o >>= 1) s += __shfl_xor_sync(0xffffffffu, s, o);
    if (lane == 0) R[row] = 1.0f / s;
}

// ---------------------------------------------------------------------------
// kernel_launch
// ---------------------------------------------------------------------------
extern "C" void kernel_launch(void* const* d_in, const int* in_sizes, int n_in,
                              void* d_out, int out_size)
{
    (void)in_sizes; (void)n_in; (void)out_size;
    const float* X  = (const float*)d_in[0];
    const float* Wq = (const float*)d_in[1];
    const float* Wk = (const float*)d_in[2];
    const float* Wv = (const float*)d_in[3];
    const float* bq = (const float*)d_in[4];
    const float* bk = (const float*)d_in[5];
    const float* bv = (const float*)d_in[6];
    float* O = (float*)d_out;

    __half *Xh, *Wh, *QKV, *P;
    float *R;
    cudaGetSymbolAddress((void**)&Xh,  g_Xh);
    cudaGetSymbolAddress((void**)&Wh,  g_Wh);
    cudaGetSymbolAddress((void**)&QKV, g_QKV);
    cudaGetSymbolAddress((void**)&P,   g_P);
    cudaGetSymbolAddress((void**)&R,   g_R);

    cudaFuncSetAttribute(gemm_h<0, 0>, cudaFuncAttributeMaxDynamicSharedMemorySize, SMEM_TOTAL);
    cudaFuncSetAttribute(gemm_h<1, 1>, cudaFuncAttributeMaxDynamicSharedMemorySize, SMEM_TOTAL);
    cudaFuncSetAttribute(gemm_h<0, 2>, cudaFuncAttributeMaxDynamicSharedMemorySize, SMEM_TOTAL);

    const size_t sQK = (size_t)2048 * 1024;
    const size_t sSS = (size_t)2048 * 2048;

    __half* Qh = QKV;
    __half* Kh = QKV + (size_t)8192 * 1024;
    __half* Vh = QKV + (size_t)2 * 8192 * 1024;

    // fp16 operand streams: X (one launch) + all 3 weights (one launch)
    f2h3<<<dim3(8192, 1), 256>>>(X, X, X, Xh, 8192 * 1024 / 4);
    f2h3<<<dim3(1024, 3), 256>>>(Wq, Wk, Wv, Wh, 1024 * 1024 / 4);

    // Fused projections: one launch computes Q, K, V (+bias), fp16
    dim3 gproj(24, 64, 1);
    gemm_h<0, 0><<<gproj, 256, SMEM_TOTAL>>>(Xh, Wh, bq, bk, bv, nullptr, QKV,
                                             1024, 1024, 0, 0, 0, 1.0f);

    // Logits -> unnormalized probs: P[b] = exp(Qh Kh^T / 32 - 4), fp16
    dim3 glog(16, 16, 4);
    gemm_h<1, 1><<<glog, 256, SMEM_TOTAL>>>(Qh, Kh, nullptr, nullptr, nullptr,
                                            nullptr, P, 2048, 1024,
                                            sQK, sQK, sSS, 0.03125f);

    // Per-row 1/sum (deterministic warp reduction)
    rowinv2048<<<1024, 256>>>(P, R);

    // Output: O[b] = (P[b] @ V[b]) * rowinv, fp32
    dim3 gout(8, 16, 4);
    gemm_h<0, 2><<<gout, 256, SMEM_TOTAL>>>(P, Vh, nullptr, nullptr, nullptr,
                                            R, O, 1024, 2048,
                                            sSS, sQK, sQK, 1.0f);
}

// round 11
// speedup vs baseline: 5.0937x; 1.1132x over previous
#include <cuda_runtime.h>
#include <cuda_fp16.h>
#include <mma.h>
#include <cstdint>
#include <cstddef>

using namespace nvcuda;

// B=4, S=2048, D=DK=DV=1024. Scratch: __device__ globals only.
__device__ __half g_Xh  [(size_t)8192 * 1024];         // fp16 X
__device__ __half g_Wh  [(size_t)3 * 1024 * 1024];     // fp16 Wq|Wk|Wv contiguous
__device__ __half g_QKV [(size_t)3 * 8192 * 1024];     // fp16 Q|K|V contiguous
__device__ __half g_P   [(size_t)4 * 2048 * 2048];     // exp(logit-4) fp16
__device__ float  g_R   [8192];                        // per-row 1/sum

__device__ __forceinline__ void cp16(uint32_t dst, const void* src) {
    asm volatile("cp.async.cg.shared.global [%0], [%1], 16;"
                 :: "r"(dst), "l"(src) : "memory");
}
__device__ __forceinline__ uint32_t smem_u32(const void* p) {
    uint32_t a;
    asm("{ .reg .u64 t; cvta.to.shared.u64 t, %1; cvt.u32.u64 %0, t; }"
        : "=r"(a) : "l"(p));
    return a;
}

// ---------------------------------------------------------------------------
// fp16 wmma GEMM, 128x128 CTA tile, BK=64, 3-stage cp.async pipeline.
// 4 warps (128 threads), warp tile 64x64 (2x2 warp grid): 0.5 fragment
// loads per MMA (vs 0.75 at 64x32) -> less L1 traffic, deeper MMA chains.
// BT=1: B is [N,K] row-major (C = A @ B^T); BT=0: B is [K,N] row-major.
// MODE 0: fused QKV projection (grid.x=24, w=x>>3): out = half(v + bias[col])
// MODE 1: out = half(exp(v*scale - 4))   (logits -> unnormalized probs)
// MODE 2: out = float(v * rowinv[row])   (AV, normalized)
// Row strides: A/B-trans 72 halves (144 B ≡ 16 mod 128 -> conflict-free),
// B non-trans 136 halves (272 B ≡ 16 mod 128).
// ---------------------------------------------------------------------------
constexpr int LDA   = 72;
constexpr int LDBN  = 136;
constexpr int STAGE = 36864;
constexpr int SMEM_TOTAL = 3 * STAGE;  // 110592 -> 2 CTAs/SM

template <int BT, int MODE>
__global__ void __launch_bounds__(128, 2) gemm_h(
    const __half* __restrict__ A, const __half* __restrict__ Bm,
    const float* __restrict__ bq, const float* __restrict__ bk,
    const float* __restrict__ bv, const float* __restrict__ rowinv,
    void* __restrict__ Cv,
    int N_, int K, size_t strA, size_t strB, size_t strC, float scale)
{
    extern __shared__ char smem[];
    const uint32_t sbase = smem_u32(smem);
    const int tid = threadIdx.x, wid = tid >> 5, lane = tid & 31;

    const float* bias = nullptr;
    int n0;
    if (MODE == 0) {
        const int w = blockIdx.x >> 3;
        n0 = (blockIdx.x & 7) * 128;
        Bm += (size_t)w * 1048576;                    // w-th weight matrix
        Cv = (void*)((__half*)Cv + (size_t)w * 8388608);
        bias = (w == 0) ? bq : (w == 1) ? bk : bv;
    } else {
        n0 = blockIdx.x * 128;
        A  += (size_t)blockIdx.z * strA;
        Bm += (size_t)blockIdx.z * strB;
    }
    const int m0 = blockIdx.y * 128;
    const int mw = (wid >> 1) * 64;   // warp row offset (2x2 warp grid)
    const int nw = (wid & 1) * 64;    // warp col offset
    const int nch = K >> 6;

    wmma::fragment<wmma::accumulator, 16, 16, 16, float> acc[4][4];
#pragma unroll
    for (int i = 0; i < 4; i++)
#pragma unroll
        for (int j = 0; j < 4; j++) wmma::fill_fragment(acc[i][j], 0.0f);

    auto load_chunk = [&](int c, int s) {
        const uint32_t sA = sbase + (uint32_t)s * STAGE;
        const uint32_t sB = sA + 18432u;
#pragma unroll
        for (int i = 0; i < 8; i++) {                 // A: 128 rows x 64 halves
            int lin = tid + i * 128;
            int r = lin >> 3, c8 = (lin & 7) * 8;
            cp16(sA + (uint32_t)(r * 144 + c8 * 2),
                 A + (size_t)(m0 + r) * K + c * 64 + c8);
        }
        if (BT) {                                     // B: 128 rows x 64 halves
#pragma unroll
            for (int i = 0; i < 8; i++) {
                int lin = tid + i * 128;
                int r = lin >> 3, c8 = (lin & 7) * 8;
                cp16(sB + (uint32_t)(r * 144 + c8 * 2),
                     Bm + (size_t)(n0 + r) * K + c * 64 + c8);
            }
        } else {                                      // B: 64 rows x 128 halves
#pragma unroll
            for (int i = 0; i < 8; i++) {
                int lin = tid + i * 128;
                int r = lin >> 4, c8 = (lin & 15) * 8;
                cp16(sB + (uint32_t)(r * 272 + c8 * 2),
                     Bm + (size_t)(c * 64 + r) * N_ + n0 + c8);
            }
        }
    };

    auto compute = [&](int s) {
        const __half* hA = reinterpret_cast<const __half*>(smem + (size_t)s * STAGE);
        const __half* hB = reinterpret_cast<const __half*>(smem + (size_t)s * STAGE + 18432);
#pragma unroll
        for (int ko = 0; ko < 4; ko++) {
            wmma::fragment<wmma::matrix_a, 16, 16, 16, __half, wmma::row_major> af[4];
#pragma unroll
            for (int i = 0; i < 4; i++)
                wmma::load_matrix_sync(af[i], hA + (mw + i * 16) * LDA + ko * 16, LDA);
            // Load one B fragment at a time; reuse all 4 A fragments against it.
#pragma unroll
            for (int j = 0; j < 4; j++) {
                if (BT) {
                    wmma::fragment<wmma::matrix_b, 16, 16, 16, __half, wmma::col_major> bf;
                    wmma::load_matrix_sync(bf, hB + (nw + j * 16) * LDA + ko * 16, LDA);
#pragma unroll
                    for (int i = 0; i < 4; i++)
                        wmma::mma_sync(acc[i][j], af[i], bf, acc[i][j]);
                } else {
                    wmma::fragment<wmma::matrix_b, 16, 16, 16, __half, wmma::row_major> bf;
                    wmma::load_matrix_sync(bf, hB + (ko * 16) * LDBN + nw + j * 16, LDBN);
#pragma unroll
                    for (int i = 0; i < 4; i++)
                        wmma::mma_sync(acc[i][j], af[i], bf, acc[i][j]);
                }
            }
        }
    };

    load_chunk(0, 0);
    asm volatile("cp.async.commit_group;" ::: "memory");
    load_chunk(1, 1);
    asm volatile("cp.async.commit_group;" ::: "memory");

    for (int c = 0; c < nch; c++) {
        asm volatile("cp.async.wait_group 1;" ::: "memory");
        __syncthreads();
        if (c + 2 < nch) load_chunk(c + 2, (c + 2) % 3);
        asm volatile("cp.async.commit_group;" ::: "memory");
        compute(c % 3);
    }
    __syncthreads();

    // Epilogue: per-warp 16x16 staging, vectorized 4-wide stores.
    float* stg = reinterpret_cast<float*>(smem) + wid * 16 * 20;
#pragma unroll
    for (int i = 0; i < 4; i++) {
#pragma unroll
        for (int j = 0; j < 4; j++) {
            wmma::store_matrix_sync(stg, acc[i][j], 20, wmma::mem_row_major);
            __syncwarp();
#pragma unroll
            for (int l = 0; l < 2; l++) {
                const int item = lane + l * 32;
                const int r = item >> 2, g = item & 3;
                const int row = m0 + mw + i * 16 + r;
                const int col = n0 + nw + j * 16 + g * 4;
                const size_t idx = (size_t)blockIdx.z * strC + (size_t)row * N_ + col;
                float4 v = *reinterpret_cast<const float4*>(&stg[r * 20 + g * 4]);
                if (MODE == 0) {
                    const float4 b4 = *reinterpret_cast<const float4*>(&bias[col]);
                    __half2 h0 = __floats2half2_rn(v.x + b4.x, v.y + b4.y);
                    __half2 h1 = __floats2half2_rn(v.z + b4.z, v.w + b4.w);
                    uint2 u = {*reinterpret_cast<uint32_t*>(&h0),
                               *reinterpret_cast<uint32_t*>(&h1)};
                    *reinterpret_cast<uint2*>((__half*)Cv + idx) = u;
                } else if (MODE == 1) {
                    __half2 h0 = __floats2half2_rn(__expf(v.x * scale - 4.0f),
                                                   __expf(v.y * scale - 4.0f));
                    __half2 h1 = __floats2half2_rn(__expf(v.z * scale - 4.0f),
                                                   __expf(v.w * scale - 4.0f));
                    uint2 u = {*reinterpret_cast<uint32_t*>(&h0),
                               *reinterpret_cast<uint32_t*>(&h1)};
                    *reinterpret_cast<uint2*>((__half*)Cv + idx) = u;
                } else {
                    const float rv = rowinv[blockIdx.z * 2048 + row];
                    v.x *= rv; v.y *= rv; v.z *= rv; v.w *= rv;
                    *reinterpret_cast<float4*>((float*)Cv + idx) = v;
                }
            }
            __syncwarp();
        }
    }
}

// ---------------------------------------------------------------------------
// fp32 -> fp16 conversion. grid.y selects among up to 3 source matrices.
// ---------------------------------------------------------------------------
__global__ void __launch_bounds__(256) f2h3(const float* __restrict__ s0,
                                            const float* __restrict__ s1,
                                            const float* __restrict__ s2,
                                            __half* __restrict__ out,
                                            int n4_per)
{
    const int z = blockIdx.y;
    const float* in = (z == 0) ? s0 : (z == 1) ? s1 : s2;
    __half* dst = out + (size_t)z * n4_per * 4;
    int i = blockIdx.x * blockDim.x + threadIdx.x;
    if (i < n4_per) {
        float4 v = reinterpret_cast<const float4*>(in)[i];
        __half2 h0 = __floats2half2_rn(v.x, v.y);
        __half2 h1 = __floats2half2_rn(v.z, v.w);
        uint2 u;
        u.x = *reinterpret_cast<uint32_t*>(&h0);
        u.y = *reinterpret_cast<uint32_t*>(&h1);
        reinterpret_cast<uint2*>(dst)[i] = u;
    }
}

// ---------------------------------------------------------------------------
// Per-row inverse sums: one warp per row (2048 fp16 -> fp32 sum -> 1/sum).
// ---------------------------------------------------------------------------
__global__ void __launch_bounds__(256) rowinv2048(const __half* __restrict__ P,
                                                  float* __restrict__ R)
{
    const int wid = threadIdx.x >> 5, lane = threadIdx.x & 31;
    const int row = blockIdx.x * 8 + wid;
    const uint4* src = reinterpret_cast<const uint4*>(P + (size_t)row * 2048);

    float s = 0.0f;
#pragma unroll
    for (int it = 0; it < 8; it++) {
        uint4 u = src[lane + it * 32];
#pragma unroll
        for (int q = 0; q < 4; q++) {
            uint32_t w = (q == 0) ? u.x : (q == 1) ? u.y : (q == 2) ? u.z : u.w;
            float2 f = __half22float2(*reinterpret_cast<__half2*>(&w));
            s += f.x + f.y;
        }
    }
#pragma unroll
    for (int o = 16; o; o >>= 1) s += __shfl_xor_sync(0xffffffffu, s, o);
    if (lane == 0) R[row] = 1.0f / s;
}

// ---------------------------------------------------------------------------
// kernel_launch
// ---------------------------------------------------------------------------
extern "C" void kernel_launch(void* const* d_in, const int* in_sizes, int n_in,
                              void* d_out, int out_size)
{
    (void)in_sizes; (void)n_in; (void)out_size;
    const float* X  = (const float*)d_in[0];
    const float* Wq = (const float*)d_in[1];
    const float* Wk = (const float*)d_in[2];
    const float* Wv = (const float*)d_in[3];
    const float* bq = (const float*)d_in[4];
    const float* bk = (const float*)d_in[5];
    const float* bv = (const float*)d_in[6];
    float* O = (float*)d_out;

    __half *Xh, *Wh, *QKV, *P;
    float *R;
    cudaGetSymbolAddress((void**)&Xh,  g_Xh);
    cudaGetSymbolAddress((void**)&Wh,  g_Wh);
    cudaGetSymbolAddress((void**)&QKV, g_QKV);
    cudaGetSymbolAddress((void**)&P,   g_P);
    cudaGetSymbolAddress((void**)&R,   g_R);

    cudaFuncSetAttribute(gemm_h<0, 0>, cudaFuncAttributeMaxDynamicSharedMemorySize, SMEM_TOTAL);
    cudaFuncSetAttribute(gemm_h<1, 1>, cudaFuncAttributeMaxDynamicSharedMemorySize, SMEM_TOTAL);
    cudaFuncSetAttribute(gemm_h<0, 2>, cudaFuncAttributeMaxDynamicSharedMemorySize, SMEM_TOTAL);

    const size_t sQK = (size_t)2048 * 1024;
    const size_t sSS = (size_t)2048 * 2048;

    __half* Qh = QKV;
    __half* Kh = QKV + (size_t)8192 * 1024;
    __half* Vh = QKV + (size_t)2 * 8192 * 1024;

    // fp16 operand streams: X (one launch) + all 3 weights (one launch)
    f2h3<<<dim3(8192, 1), 256>>>(X, X, X, Xh, 8192 * 1024 / 4);
    f2h3<<<dim3(1024, 3), 256>>>(Wq, Wk, Wv, Wh, 1024 * 1024 / 4);

    // Fused projections: one launch computes Q, K, V (+bias), fp16
    dim3 gproj(24, 64, 1);
    gemm_h<0, 0><<<gproj, 128, SMEM_TOTAL>>>(Xh, Wh, bq, bk, bv, nullptr, QKV,
                                             1024, 1024, 0, 0, 0, 1.0f);

    // Logits -> unnormalized probs: P[b] = exp(Qh Kh^T / 32 - 4), fp16
    dim3 glog(16, 16, 4);
    gemm_h<1, 1><<<glog, 128, SMEM_TOTAL>>>(Qh, Kh, nullptr, nullptr, nullptr,
                                            nullptr, P, 2048, 1024,
                                            sQK, sQK, sSS, 0.03125f);

    // Per-row 1/sum (deterministic warp reduction)
    rowinv2048<<<1024, 256>>>(P, R);

    // Output: O[b] = (P[b] @ V[b]) * rowinv, fp32
    dim3 gout(8, 16, 4);
    gemm_h<0, 2><<<gout, 128, SMEM_TOTAL>>>(P, Vh, nullptr, nullptr, nullptr,
                                            R, O, 1024, 2048,
                                            sSS, sQK, sQK, 1.0f);
}